// round 17
// baseline (speedup 1.0000x reference)
#include <cuda_runtime.h>
#include <math.h>

#define N_DIM    64
#define B_ROWS   1024
#define QCH2     16                // kde chunks of 64 queries
#define NGRP     32                // knn row-groups of 32
#define NQ       4                 // j-quarters (256 js each)
#define NBLK_KNN (NGRP * NQ)       // 128
#define NBLK_K2  1024              // 64 cols x 16 chunks; 1 chunk per block
#define TS       3.5f              // truncation radius, h-units
#define K2C      (-0.72134752f)    // -0.5*log2(e)
#define NMOM     10                // Hermite terms 0..9

// Scratch (device globals — no allocation allowed)
__device__ float g_logrho[B_ROWS];
__device__ float g_cols[N_DIM * B_ROWS];   // sorted columns, scaled by 1/h
__device__ float g_invh[N_DIM];
__device__ float g_partials[N_DIM * QCH2];
__device__ float g_t6[NGRP][NQ][32][6];
__device__ int   g_qc[NGRP];               // self-resetting quarter counters
__device__ int   g_colc[N_DIM];            // per-column completion (16 each)
__device__ int   g_done;                   // master counter (64 contenders)

__device__ __forceinline__ float ex2(float x) {
    float r;
    asm("ex2.approx.ftz.f32 %0, %1;" : "=f"(r) : "f"(x));
    return r;
}

// ---------------------------------------------------------------------------
// Kernel 1: knn (blocks 0..127) + prep (blocks 128..191), 256 threads.
// (unchanged — best measured)
// ---------------------------------------------------------------------------
struct KnnS {
    float tile[128][68];   // stride 68: conflict-free LDS.128
    float xq[32][64];
    float jn[128];
    float qn[32];
    int   merge;
};
struct PrepS {
    float u[B_ROWS];
    float red[256];
    float scale;
};

__global__ __launch_bounds__(256)
void k1(const float* __restrict__ act, const int* __restrict__ kp) {
    __shared__ __align__(16) char sm[sizeof(KnnS) > sizeof(PrepS) ? sizeof(KnnS) : sizeof(PrepS)];
    const int tid = threadIdx.x;
    const int bx  = blockIdx.x;

    if (bx < NBLK_KNN) {
        KnnS* S = (KnnS*)sm;
        const int g = bx >> 2, q = bx & 3;
        const int row0 = g * 32, jbase = q * 256;
        const int lane = tid & 31, w = tid >> 5;

        // 32 query rows + norms (half-warp shuffle reduce)
        {
            const float4* qsrc = (const float4*)(act + row0 * N_DIM);
            #pragma unroll
            for (int t = 0; t < 2; t++) {
                int fi = tid + t * 256;
                float4 v = qsrc[fi];
                ((float4*)S->xq)[fi] = v;
                float s = v.x * v.x + v.y * v.y + v.z * v.z + v.w * v.w;
                s += __shfl_down_sync(0xffffffffu, s, 8, 16);
                s += __shfl_down_sync(0xffffffffu, s, 4, 16);
                s += __shfl_down_sync(0xffffffffu, s, 2, 16);
                s += __shfl_down_sync(0xffffffffu, s, 1, 16);
                if ((lane & 15) == 0) S->qn[fi >> 4] = s;
            }
        }

        float m[4][6];
        #pragma unroll
        for (int r = 0; r < 4; r++)
            #pragma unroll
            for (int i = 0; i < 6; i++) m[r][i] = 3.4e38f;

        for (int t = 0; t < 2; t++) {
            __syncthreads();
            const float4* gsrc = (const float4*)(act + (jbase + t * 128) * N_DIM);
            #pragma unroll
            for (int it = 0; it < 8; it++) {
                int fi = tid + it * 256;
                float4 v = gsrc[fi];
                *(float4*)&S->tile[fi >> 4][(fi & 15) * 4] = v;
                float s = v.x * v.x + v.y * v.y + v.z * v.z + v.w * v.w;
                s += __shfl_down_sync(0xffffffffu, s, 8, 16);
                s += __shfl_down_sync(0xffffffffu, s, 4, 16);
                s += __shfl_down_sync(0xffffffffu, s, 2, 16);
                s += __shfl_down_sync(0xffffffffu, s, 1, 16);
                if ((lane & 15) == 0) S->jn[fi >> 4] = s;
            }
            __syncthreads();

            float acc[4][4];
            #pragma unroll
            for (int r = 0; r < 4; r++)
                #pragma unroll
                for (int s = 0; s < 4; s++) acc[r][s] = 0.f;

            #pragma unroll
            for (int c = 0; c < 8; c++) {      // 8-dim chunks
                float4 qr[4][2];
                #pragma unroll
                for (int r = 0; r < 4; r++) {
                    qr[r][0] = *(const float4*)&S->xq[4 * w + r][c * 8];
                    qr[r][1] = *(const float4*)&S->xq[4 * w + r][c * 8 + 4];
                }
                #pragma unroll
                for (int s = 0; s < 4; s++) {
                    const int j = lane + 32 * s;
                    const float4 b0 = *(const float4*)&S->tile[j][c * 8];
                    const float4 b1 = *(const float4*)&S->tile[j][c * 8 + 4];
                    #pragma unroll
                    for (int r = 0; r < 4; r++) {
                        float a = acc[r][s];
                        a = fmaf(qr[r][0].x, b0.x, a);
                        a = fmaf(qr[r][0].y, b0.y, a);
                        a = fmaf(qr[r][0].z, b0.z, a);
                        a = fmaf(qr[r][0].w, b0.w, a);
                        a = fmaf(qr[r][1].x, b1.x, a);
                        a = fmaf(qr[r][1].y, b1.y, a);
                        a = fmaf(qr[r][1].z, b1.z, a);
                        a = fmaf(qr[r][1].w, b1.w, a);
                        acc[r][s] = a;
                    }
                }
            }
            #pragma unroll
            for (int s = 0; s < 4; s++) {
                const float nj = S->jn[lane + 32 * s];
                #pragma unroll
                for (int r = 0; r < 4; r++) {
                    float v = fmaf(acc[r][s], -2.f, nj);
                    if (v < m[r][5]) {
                        m[r][5] = v;
                        #pragma unroll
                        for (int i = 5; i > 0; i--)
                            if (m[r][i] < m[r][i - 1]) {
                                float tm = m[r][i]; m[r][i] = m[r][i - 1]; m[r][i - 1] = tm;
                            }
                    }
                }
            }
        }

        // per-row: extract top-6 over lanes, add qn, store
        #pragma unroll
        for (int r = 0; r < 4; r++) {
            float l0 = m[r][0], l1 = m[r][1], l2 = m[r][2];
            float l3 = m[r][3], l4 = m[r][4], l5 = m[r][5];
            float keep = 3.4e38f;
            #pragma unroll
            for (int i = 0; i < 6; i++) {
                float mv = l0;
                #pragma unroll
                for (int off = 16; off; off >>= 1)
                    mv = fminf(mv, __shfl_xor_sync(0xffffffffu, mv, off));
                if (lane == i) keep = mv;
                unsigned msk = __ballot_sync(0xffffffffu, l0 == mv);
                if (lane == (__ffs(msk) - 1)) {
                    l0 = l1; l1 = l2; l2 = l3; l3 = l4; l4 = l5; l5 = 3.4e38f;
                }
            }
            if (lane < 6)
                g_t6[g][q][4 * w + r][lane] = keep + S->qn[4 * w + r];
        }
        __syncthreads();
        if (tid == 0) {
            __threadfence();
            int old = atomicAdd(&g_qc[g], 1);
            S->merge = (old == NQ - 1);
        }
        __syncthreads();
        if (S->merge) {
            __threadfence();
            if (tid < 32) {
                int kk = *kp; if (kk > 5) kk = 5;
                float best[6];
                #pragma unroll
                for (int i = 0; i < 6; i++) best[i] = 3.4e38f;
                #pragma unroll
                for (int qq = 0; qq < NQ; qq++) {
                    #pragma unroll
                    for (int i = 0; i < 6; i++) {
                        float v = g_t6[g][qq][tid][i];
                        if (v < best[5]) {
                            best[5] = v;
                            #pragma unroll
                            for (int j2 = 5; j2 > 0; j2--)
                                if (best[j2] < best[j2 - 1]) {
                                    float tm = best[j2]; best[j2] = best[j2 - 1]; best[j2 - 1] = tm;
                                }
                        }
                    }
                }
                g_logrho[row0 + tid] = logf(fmaxf(best[kk], 1e-12f));
            }
            if (tid == 0) g_qc[g] = 0;   // reset for graph replay
        }
    } else {
        // ================= PREP (256 thr, 4 elems/thread) ================
        PrepS* P = (PrepS*)sm;
        const int col = bx - NBLK_KNN;
        float s1 = 0.f, s2 = 0.f;
        #pragma unroll
        for (int t = 0; t < 4; t++) {
            float v = act[(tid + 256 * t) * N_DIM + col];
            P->u[tid + 256 * t] = v;
            s1 += v;
            s2 += v * v;
        }
        P->red[tid] = s1; __syncthreads();
        for (int st = 128; st > 0; st >>= 1) {
            if (tid < st) P->red[tid] += P->red[tid + st];
            __syncthreads();
        }
        float tot1 = P->red[0]; __syncthreads();
        P->red[tid] = s2; __syncthreads();
        for (int st = 128; st > 0; st >>= 1) {
            if (tid < st) P->red[tid] += P->red[tid + st];
            __syncthreads();
        }
        if (tid == 0) {
            const float Bf = (float)B_ROWS;
            float mean = tot1 / Bf;
            float var  = (P->red[0] - Bf * mean * mean) / (Bf - 1.0f);
            float stdv = sqrtf(fmaxf(var, 0.f));
            float h    = fmaxf(1.06f * stdv * 0.25f, 1e-4f);
            float ih   = 1.0f / h;
            g_invh[col] = ih;
            P->scale    = ih;
        }
        __syncthreads();
        const float sc = P->scale;
        #pragma unroll
        for (int t = 0; t < 4; t++)
            P->u[tid + 256 * t] *= sc;

        for (int kk2 = 2; kk2 <= B_ROWS; kk2 <<= 1) {
            for (int jj = kk2 >> 1; jj > 0; jj >>= 1) {
                __syncthreads();
                #pragma unroll
                for (int t = 0; t < 4; t++) {
                    int i = tid + 256 * t;
                    int ixj = i ^ jj;
                    if (ixj > i) {
                        bool up = ((i & kk2) == 0);
                        float a = P->u[i], b = P->u[ixj];
                        if ((a > b) == up) { P->u[i] = b; P->u[ixj] = a; }
                    }
                }
            }
        }
        __syncthreads();
        #pragma unroll
        for (int t = 0; t < 4; t++)
            g_cols[col * B_ROWS + tid + 256 * t] = P->u[tid + 256 * t];
    }
}

// ---------------------------------------------------------------------------
// Kernel 2: KDE — ONE 64-query chunk per block, 8 warps of moments
// (2-3 samples/thread), reflections folded into moments.
// grid = 1024 (col*16 + chunk), block = 256.
// ---------------------------------------------------------------------------
__global__ __launch_bounds__(256)
void k2(const int* __restrict__ kp, float* __restrict__ out) {
    __shared__ __align__(16) float u[B_ROWS];
    __shared__ float msum[8][NMOM];
    __shared__ float lsum[2];
    __shared__ int   bnd[4];
    __shared__ double dred[256];
    __shared__ int   s_col_last, s_master;

    const int tid   = threadIdx.x;
    const int lane  = tid & 31;
    const int w     = tid >> 5;
    const int col   = blockIdx.x >> 4;
    const int chunk = blockIdx.x & 15;

    ((float4*)u)[tid] = ((const float4*)(g_cols + col * B_ROWS))[tid];
    __syncthreads();

    const float ih = g_invh[col];
    const float c2 = 2.0f * ih;
    const int   q0 = chunk * 64;
    const float cen = 0.5f * (u[q0] + u[q0 + 63]);

    if (tid < 4) {
        float xmn = u[q0], xmx = u[q0 + 63];
        float tgt = (tid == 0) ? xmn - TS : (tid == 1) ? xmx + TS
                  : (tid == 2) ? TS - xmn : c2 - TS - xmx;
        int pos = 0;
        #pragma unroll
        for (int step = 1024; step; step >>= 1) {
            int np = pos + step;
            if (np <= B_ROWS && u[np - 1] < tgt) pos = np;
        }
        bnd[tid] = pos;
    }
    __syncthreads();
    const int a0 = bnd[0], b0 = bnd[1], bL = bnd[2], aR = bnd[3];

    // ---- Hermite moments over main + mirrored windows (all 8 warps) ----
    {
        constexpr float INV[NMOM] = {0.f, 1.f, 0.5f, 0.33333334f, 0.25f, 0.2f,
            0.16666667f, 0.14285715f, 0.125f, 0.11111111f};
        float M[NMOM];
        #pragma unroll
        for (int n = 0; n < NMOM; n++) M[n] = 0.f;

        #define HSTEP(arg) do {                                   \
            float uj_ = (arg);                                    \
            float wg_ = ex2(K2C * uj_ * uj_);                     \
            float bp_ = wg_, bc_ = wg_ * uj_;                     \
            M[0] += bp_; M[1] += bc_;                             \
            _Pragma("unroll")                                     \
            for (int n_ = 1; n_ < NMOM - 1; n_++) {               \
                float bn_ = fmaf(uj_, bc_, -bp_) * INV[n_ + 1];   \
                M[n_ + 1] += bn_; bp_ = bc_; bc_ = bn_;           \
            }                                                     \
        } while (0)

        for (int j = a0 + tid; j < b0; j += 256) HSTEP(u[j] - cen);
        for (int j = tid; j < bL; j += 256)      HSTEP(-u[j] - cen);
        for (int j = aR + tid; j < B_ROWS; j += 256) HSTEP(c2 - u[j] - cen);
        #undef HSTEP

        #pragma unroll
        for (int n = 0; n < NMOM; n++) {
            #pragma unroll
            for (int off = 16; off; off >>= 1)
                M[n] += __shfl_xor_sync(0xffffffffu, M[n], off);
        }
        if (lane == 0) {
            #pragma unroll
            for (int n = 0; n < NMOM; n++) msum[w][n] = M[n];
        }
    }
    __syncthreads();

    // ---- per-query Horner (warps 0,1: queries 0-31 / 32-63) ----
    if (w < 2) {
        float Mn[NMOM];
        #pragma unroll
        for (int n = 0; n < NMOM; n++)
            Mn[n] = ((msum[0][n] + msum[1][n]) + (msum[2][n] + msum[3][n]))
                  + ((msum[4][n] + msum[5][n]) + (msum[6][n] + msum[7][n]));
        const float x = u[q0 + w * 32 + lane];
        const float delta = x - cen;
        float f = Mn[NMOM - 1];
        #pragma unroll
        for (int n = NMOM - 2; n >= 0; n--)
            f = fmaf(f, delta, Mn[n]);

        const float Bf = (float)B_ROWS;
        const float scale = ih * (1.0f / (Bf * 2.5066282746310002f));
        float l = logf(f * scale + 1e-8f);
        #pragma unroll
        for (int off = 16; off; off >>= 1)
            l += __shfl_xor_sync(0xffffffffu, l, off);
        if (lane == 0) lsum[w] = l;
    }
    __syncthreads();
    if (tid == 0)
        g_partials[col * QCH2 + chunk] = lsum[0] + lsum[1];

    // ---- hierarchical completion ----
    __syncthreads();
    if (tid == 0) {
        __threadfence();
        int old = atomicAdd(&g_colc[col], 1);
        s_col_last = (old == 15);
    }
    __syncthreads();
    if (!s_col_last) return;
    __threadfence();

    // column winner: assemble this column's marginal entropy
    if (tid < 32) {
        float t = (tid < QCH2) ? g_partials[col * QCH2 + tid] : 0.f;
        #pragma unroll
        for (int off = 16; off; off >>= 1)
            t += __shfl_xor_sync(0xffffffffu, t, off);
        if (tid == 0) {
            out[1 + col] = -t / (float)B_ROWS;
            g_colc[col] = 0;   // reset for graph replay
        }
    }
    __syncthreads();
    if (tid == 0) {
        __threadfence();
        int old = atomicAdd(&g_done, 1);
        s_master = (old == N_DIM - 1);
    }
    __syncthreads();
    if (!s_master) return;
    __threadfence();

    // master: fp64 joint entropy
    {
        double s = 0.0;
        for (int i = tid; i < B_ROWS; i += 256) s += (double)g_logrho[i];
        dred[tid] = s; __syncthreads();
        for (int st = 128; st > 0; st >>= 1) {
            if (tid < st) dred[tid] += dred[tid + st];
            __syncthreads();
        }
        if (tid == 0) {
            const int k = *kp;
            const double EULER    = 0.5772156649015328606;
            const double DG_B     = 6.9309834448765934;     // psi(1024)
            const double LGAMMA33 = 81.55795945611503558;   // lgamma(64/2+1)
            const double LOG_PI   = 1.1447298858494001741;
            const double INV_LN2  = 1.4426950408889634074;
            double dg_k = -EULER;
            for (int i = 1; i < k; i++) dg_k += 1.0 / (double)i;
            double log_c_d = 0.5 * (double)N_DIM * LOG_PI - LGAMMA33;
            double mean_lr = dred[0] / (double)B_ROWS;
            double h_nats = -dg_k + DG_B + log_c_d + (double)N_DIM * 0.5 * mean_lr;
            out[0] = (float)(h_nats * INV_LN2);
            g_done = 0;   // reset for graph replay
        }
    }
}

// ---------------------------------------------------------------------------
extern "C" void kernel_launch(void* const* d_in, const int* in_sizes, int n_in,
                              void* d_out, int out_size) {
    const float* act = (const float*)d_in[0];
    const int*   kp  = (const int*)d_in[1];
    float* out = (float*)d_out;
    (void)in_sizes; (void)n_in; (void)out_size;

    k1<<<NBLK_KNN + N_DIM, 256>>>(act, kp);
    k2<<<NBLK_K2, 256>>>(kp, out);
}